// round 1
// baseline (speedup 1.0000x reference)
#include <cuda_runtime.h>
#include <cuda_bf16.h>

#define WARPS 4
#define THREADS (WARPS*32)
#define NN 29
#define KK 6
#define C1 26    // edge hidden 1
#define C1P 28   // padded to float4 multiple
#define MM 32    // m_dim
#define H2 12    // node hidden
#define NROW 40  // padded transposed Wn1 row: [6 feats][2 pad][32 m]

__device__ __forceinline__ float fsigmoid(float v){
    float e = __expf(-v);
    return __fdividef(1.0f, 1.0f + e);
}
__device__ __forceinline__ float fsilu(float v){
    return v * fsigmoid(v);
}

__global__ void __launch_bounds__(THREADS)
arnet_kernel(const float* __restrict__ x,
             const float* __restrict__ We1, const float* __restrict__ be1,
             const float* __restrict__ We2, const float* __restrict__ be2,
             const float* __restrict__ Wg,  const float* __restrict__ bgp,
             const float* __restrict__ Wn1, const float* __restrict__ bn1,
             const float* __restrict__ Wn2, const float* __restrict__ bn2,
             const float* __restrict__ Wm1, const float* __restrict__ bm1,
             const float* __restrict__ Wm2, const float* __restrict__ bm2,
             float* __restrict__ out, int Btot)
{
    __shared__ float sWe1[13*C1];
    __shared__ float sbe1[C1];
    __shared__ __align__(16) float sw13[C1P];
    __shared__ __align__(16) float sWe2[C1P*MM];
    __shared__ __align__(16) float sbe2[MM];
    __shared__ __align__(16) float sWg[MM];
    __shared__ float sbg;
    __shared__ __align__(16) float sWn1t[H2*NROW];
    __shared__ float sbn1[H2];
    __shared__ float sWn2[H2*6];
    __shared__ float sbn2[6];
    __shared__ float sWm1[6*MM];
    __shared__ float sbm1[MM];
    __shared__ float sWm2[MM*H2];
    __shared__ float sbm2[H2];
    __shared__ __align__(16) float sx[WARPS][NN*3 + 1];
    __shared__ __align__(16) float su[WARPS][NN*C1P];
    __shared__ __align__(16) float sv[WARPS][NN*C1P];
    __shared__ float shid[WARPS][MM];

    const int tid = threadIdx.x;

    // ---- cooperative weight staging ----
    for (int t = tid; t < 13*C1; t += THREADS) sWe1[t] = We1[t];
    for (int t = tid; t < C1;    t += THREADS) sbe1[t] = be1[t];
    for (int t = tid; t < C1P;   t += THREADS) sw13[t] = (t < C1) ? We1[12*C1 + t] : 0.0f;
    for (int t = tid; t < C1P*MM; t += THREADS) sWe2[t] = (t < C1*MM) ? We2[t] : 0.0f;
    for (int t = tid; t < MM; t += THREADS){ sbe2[t] = be2[t]; sWg[t] = Wg[t]; sbm1[t] = bm1[t]; }
    if (tid == 0) sbg = bgp[0];
    for (int t = tid; t < H2*NROW; t += THREADS){
        int c = t / NROW, r = t % NROW;
        float v = 0.0f;
        if (r < 6) v = Wn1[r*H2 + c];
        else if (r >= 8 && r < 8+MM) v = Wn1[(6 + (r-8))*H2 + c];
        sWn1t[t] = v;
    }
    for (int t = tid; t < H2;   t += THREADS){ sbn1[t] = bn1[t]; sbm2[t] = bm2[t]; }
    for (int t = tid; t < H2*6; t += THREADS) sWn2[t] = Wn2[t];
    for (int t = tid; t < 6;    t += THREADS) sbn2[t] = bn2[t];
    for (int t = tid; t < 6*MM; t += THREADS) sWm1[t] = Wm1[t];
    for (int t = tid; t < MM*H2; t += THREADS) sWm2[t] = Wm2[t];
    __syncthreads();

    const int w = tid >> 5, lane = tid & 31;
    const int b = blockIdx.x * WARPS + w;
    if (b >= Btot) return;

    float* sxw = sx[w];
    {
        const float* xb = x + (size_t)b * (NN*3);
        for (int t = lane; t < NN*3; t += 32) sxw[t] = xb[t];
    }
    __syncwarp();

    const bool active = lane < NN;
    const int i = active ? lane : (NN-1);   // dummies shadow node 28 (results discarded)
    const float xi0 = sxw[i*3+0], xi1 = sxw[i*3+1], xi2 = sxw[i*3+2];

    // ---- KNN: 6 smallest squared dists, stable (lower index wins ties) ----
    float bdist[KK]; int bidx[KK];
#pragma unroll
    for (int s = 0; s < KK; ++s){ bdist[s] = 3.4e38f; bidx[s] = 0; }
    for (int j = 0; j < NN; ++j){
        float dx = xi0 - sxw[j*3+0];
        float dy = xi1 - sxw[j*3+1];
        float dz = xi2 - sxw[j*3+2];
        float dd = dx*dx + dy*dy + dz*dz;
        if (dd < bdist[KK-1]){
            bdist[KK-1] = dd; bidx[KK-1] = j;
#pragma unroll
            for (int s = KK-1; s > 0; --s){
                if (bdist[s] < bdist[s-1]){
                    float td = bdist[s]; bdist[s] = bdist[s-1]; bdist[s-1] = td;
                    int tj = bidx[s]; bidx[s] = bidx[s-1]; bidx[s-1] = tj;
                }
            }
        }
    }
    // copy to dynamically-indexed arrays for the edge loop
    float nd[KK]; int nj[KK];
#pragma unroll
    for (int s = 0; s < KK; ++s){ nd[s] = bdist[s]; nj[s] = bidx[s]; }

    // ---- per-node u_i / v_j tables (edge_in@We1 factored) ----
    {
        float* surow = su[w] + i*C1P;
        float* svrow = sv[w] + i*C1P;
#pragma unroll 1
        for (int c = 0; c < C1; ++c){
            float a0 = sWe1[0*C1+c] + sWe1[3*C1+c];
            float a1 = sWe1[1*C1+c] + sWe1[4*C1+c];
            float a2 = sWe1[2*C1+c] + sWe1[5*C1+c];
            float b0 = sWe1[6*C1+c] + sWe1[ 9*C1+c];
            float b1 = sWe1[7*C1+c] + sWe1[10*C1+c];
            float b2 = sWe1[8*C1+c] + sWe1[11*C1+c];
            surow[c] = sbe1[c] + xi0*a0 + xi1*a1 + xi2*a2;
            svrow[c] = xi0*b0 + xi1*b1 + xi2*b2;
        }
        surow[26] = 0.0f; surow[27] = 0.0f;
        svrow[26] = 0.0f; svrow[27] = 0.0f;
    }
    __syncwarp();

    // ---- edge loop: 6 neighbors, 26->32 GEMV + gate, accumulate m_i ----
    float macc[MM];
#pragma unroll
    for (int r = 0; r < MM; ++r) macc[r] = 0.0f;

    const float4* w13v = (const float4*)sw13;
    const float4* be2v = (const float4*)sbe2;
    const float4* uvec = (const float4*)(su[w] + i*C1P);

    for (int k = 0; k < KK; ++k){
        const float d = nd[k];
        const int   j = nj[k];
        const float4* vvec = (const float4*)(sv[w] + j*C1P);

        float m[MM];
#pragma unroll
        for (int q = 0; q < MM/4; ++q){
            float4 bb = be2v[q];
            m[4*q+0] = bb.x; m[4*q+1] = bb.y; m[4*q+2] = bb.z; m[4*q+3] = bb.w;
        }
#pragma unroll
        for (int cc = 0; cc < C1P/4; ++cc){
            float4 uu = uvec[cc];
            float4 vv = vvec[cc];
            float4 ww = w13v[cc];
            float h0 = fsilu(uu.x + vv.x + d*ww.x);
            float h1 = fsilu(uu.y + vv.y + d*ww.y);
            float h2 = fsilu(uu.z + vv.z + d*ww.z);
            float h3 = fsilu(uu.w + vv.w + d*ww.w);
            const float4* wr0 = (const float4*)(sWe2 + (cc*4+0)*MM);
            const float4* wr1 = (const float4*)(sWe2 + (cc*4+1)*MM);
            const float4* wr2 = (const float4*)(sWe2 + (cc*4+2)*MM);
            const float4* wr3 = (const float4*)(sWe2 + (cc*4+3)*MM);
#pragma unroll
            for (int q = 0; q < MM/4; ++q){
                float4 w0 = wr0[q], w1 = wr1[q], w2 = wr2[q], w3 = wr3[q];
                m[4*q+0] += h0*w0.x; m[4*q+0] += h1*w1.x; m[4*q+0] += h2*w2.x; m[4*q+0] += h3*w3.x;
                m[4*q+1] += h0*w0.y; m[4*q+1] += h1*w1.y; m[4*q+1] += h2*w2.y; m[4*q+1] += h3*w3.y;
                m[4*q+2] += h0*w0.z; m[4*q+2] += h1*w1.z; m[4*q+2] += h2*w2.z; m[4*q+2] += h3*w3.z;
                m[4*q+3] += h0*w0.w; m[4*q+3] += h1*w1.w; m[4*q+3] += h2*w2.w; m[4*q+3] += h3*w3.w;
            }
        }
        // silu + soft edge gate
        float g = sbg;
#pragma unroll
        for (int r = 0; r < MM; ++r){
            m[r] = fsilu(m[r]);
            g += m[r] * sWg[r];
        }
        g = fsigmoid(g);
#pragma unroll
        for (int r = 0; r < MM; ++r) macc[r] += m[r] * g;
    }

    // ---- node MLP 38->12->6 + residual ----
    float fo[6];
    {
        float h12[H2];
#pragma unroll 1
        for (int c = 0; c < H2; ++c){
            const float* row = sWn1t + c*NROW;
            float acc = sbn1[c];
            acc += xi0*row[0]; acc += xi1*row[1]; acc += xi2*row[2];
            acc += xi0*row[3]; acc += xi1*row[4]; acc += xi2*row[5];
            const float4* rowv = (const float4*)(row + 8);
#pragma unroll
            for (int q = 0; q < MM/4; ++q){
                float4 wv = rowv[q];
                acc += macc[4*q+0]*wv.x; acc += macc[4*q+1]*wv.y;
                acc += macc[4*q+2]*wv.z; acc += macc[4*q+3]*wv.w;
            }
            h12[c] = fsilu(acc);
        }
#pragma unroll
        for (int o = 0; o < 6; ++o){
            float acc = sbn2[o];
#pragma unroll
            for (int c = 0; c < H2; ++c) acc += h12[c]*sWn2[c*6+o];
            float base = (o % 3 == 0) ? xi0 : ((o % 3 == 1) ? xi1 : xi2);
            fo[o] = acc + base;
        }
    }
    if (!active){
#pragma unroll
        for (int o = 0; o < 6; ++o) fo[o] = 0.0f;
    }

    // ---- masked mean pool across 29 nodes (butterfly, all lanes get result) ----
#pragma unroll
    for (int o = 0; o < 6; ++o){
#pragma unroll
        for (int off = 16; off > 0; off >>= 1)
            fo[o] += __shfl_xor_sync(0xffffffffu, fo[o], off);
        fo[o] *= (1.0f / 29.0f);
    }

    // ---- head MLP 6->32 (relu) ->12, plus zero padding of rows 2..28 ----
    float hid = sbm1[lane];
#pragma unroll
    for (int c = 0; c < 6; ++c) hid += fo[c]*sWm1[c*MM + lane];
    hid = fmaxf(hid, 0.0f);
    shid[w][lane] = hid;
    __syncwarp();

    float* ob = out + (size_t)b * (NN*6);
    if (lane < H2){
        float acc = sbm2[lane];
#pragma unroll
        for (int h = 0; h < MM; ++h) acc += shid[w][h]*sWm2[h*H2 + lane];
        ob[lane] = acc;
    }
    for (int t = H2 + lane; t < NN*6; t += 32) ob[t] = 0.0f;
}

extern "C" void kernel_launch(void* const* d_in, const int* in_sizes, int n_in,
                              void* d_out, int out_size)
{
    const float* x   = (const float*)d_in[0];
    // d_in[1] = mask (all-true in this problem; edge/pair masks are no-ops)
    const float* We1 = (const float*)d_in[2];
    const float* be1 = (const float*)d_in[3];
    const float* We2 = (const float*)d_in[4];
    const float* be2 = (const float*)d_in[5];
    const float* Wg  = (const float*)d_in[6];
    const float* bg  = (const float*)d_in[7];
    const float* Wn1 = (const float*)d_in[8];
    const float* bn1 = (const float*)d_in[9];
    const float* Wn2 = (const float*)d_in[10];
    const float* bn2 = (const float*)d_in[11];
    const float* Wm1 = (const float*)d_in[12];
    const float* bm1 = (const float*)d_in[13];
    const float* Wm2 = (const float*)d_in[14];
    const float* bm2 = (const float*)d_in[15];

    int B = in_sizes[0] / (NN*3);
    int grid = (B + WARPS - 1) / WARPS;
    arnet_kernel<<<grid, THREADS>>>(x, We1, be1, We2, be2, Wg, bg,
                                    Wn1, bn1, Wn2, bn2, Wm1, bm1, Wm2, bm2,
                                    (float*)d_out, B);
}

// round 2
// speedup vs baseline: 5.3550x; 5.3550x over previous
#include <cuda_runtime.h>

#define TPB   128
#define NN    29
#define SLOTS 32
#define KK    6
#define C1    26
#define C1P   28
#define MM    32
#define H2    12
#define MROW  36   // padded sm row stride (floats)
#define NROW  36   // padded Wn1-folded row stride

typedef unsigned long long ull;

__device__ __forceinline__ void ffma2(ull& d, ull a, ull b){
    asm("fma.rn.f32x2 %0, %1, %2, %0;" : "+l"(d) : "l"(a), "l"(b));
}
__device__ __forceinline__ ull splat2(float x){
    ull r; asm("mov.b64 %0, {%1, %1};" : "=l"(r) : "f"(x)); return r;
}
__device__ __forceinline__ ull pack2(float x, float y){
    ull r; asm("mov.b64 %0, {%1, %2};" : "=l"(r) : "f"(x), "f"(y)); return r;
}
__device__ __forceinline__ float2 unpack2(ull v){
    float2 f; asm("mov.b64 {%0, %1}, %2;" : "=f"(f.x), "=f"(f.y) : "l"(v)); return f;
}
__device__ __forceinline__ float fsigmoid(float v){
    return __fdividef(1.0f, 1.0f + __expf(-v));
}
__device__ __forceinline__ float fsilu(float v){
    return __fdividef(v, 1.0f + __expf(-v));
}

__global__ void __launch_bounds__(TPB, 6)
arnet_kernel(const float* __restrict__ x,
             const float* __restrict__ We1, const float* __restrict__ be1,
             const float* __restrict__ We2, const float* __restrict__ be2,
             const float* __restrict__ Wg,  const float* __restrict__ bgp,
             const float* __restrict__ Wn1, const float* __restrict__ bn1,
             const float* __restrict__ Wn2, const float* __restrict__ bn2,
             const float* __restrict__ Wm1, const float* __restrict__ bm1,
             const float* __restrict__ Wm2, const float* __restrict__ bm2,
             float* __restrict__ out)
{
    // ---- weights (per-block staged) ----
    __shared__ __align__(16) float sWab[C1*8];      // folded We1: [c][a0,a1,a2,b0,b1,b2,0,0]
    __shared__ float sbe1[C1P];
    __shared__ float sw13[C1P];
    __shared__ __align__(16) float sWe2[C1P*MM];    // [28][32], rows 26,27 zero
    __shared__ __align__(16) float sbe2[MM];
    __shared__ __align__(16) float sWg[MM];
    __shared__ float sbg;
    __shared__ __align__(16) float sWn1f[H2*NROW];  // [12][3 folded feats,1 pad,32 m]
    __shared__ float sbn1[H2];
    __shared__ float sWn2[H2*6];
    __shared__ float sbn2[8];
    __shared__ float sWm1[6*MM];
    __shared__ float sbm1[MM];
    __shared__ float sWm2[MM*H2];
    __shared__ float sbm2[H2];
    // ---- per-batch scratch ----
    __shared__ __align__(16) float sx[SLOTS*3];
    __shared__ __align__(16) float sv[SLOTS*C1P];   // v_j table
    __shared__ __align__(16) float sh[SLOTS*C1P];   // per-edge h vector
    __shared__ __align__(16) float sm[SLOTS*MROW];  // m_i (32 per node)
    __shared__ __align__(16) float sh12[SLOTS*H2];
    __shared__ float sfo[SLOTS*6];
    __shared__ float snd[SLOTS*KK];
    __shared__ int   snj[SLOTS*KK];
    __shared__ float shid[MM];

    const int tid = threadIdx.x;
    const int b   = blockIdx.x;

    // ================= staging =================
    for (int t = tid; t < C1*8; t += TPB){
        int c = t >> 3, k = t & 7; float v = 0.0f;
        if (k < 3)      v = We1[k*C1 + c]     + We1[(k+3)*C1 + c];
        else if (k < 6) v = We1[(k+3)*C1 + c] + We1[(k+6)*C1 + c];
        sWab[t] = v;
    }
    for (int t = tid; t < C1P; t += TPB){
        sbe1[t] = (t < C1) ? be1[t] : 0.0f;
        sw13[t] = (t < C1) ? We1[12*C1 + t] : 0.0f;
    }
    for (int t = tid; t < C1P*MM; t += TPB) sWe2[t] = (t < C1*MM) ? We2[t] : 0.0f;
    for (int t = tid; t < MM; t += TPB){ sbe2[t] = be2[t]; sWg[t] = Wg[t]; sbm1[t] = bm1[t]; }
    if (tid == 0) sbg = bgp[0];
    for (int t = tid; t < H2*NROW; t += TPB){
        int c = t / NROW, r = t % NROW; float v = 0.0f;
        if (r < 3)       v = Wn1[r*H2 + c] + Wn1[(r+3)*H2 + c];
        else if (r >= 4) v = Wn1[(6 + (r-4))*H2 + c];
        sWn1f[t] = v;
    }
    for (int t = tid; t < H2; t += TPB){ sbn1[t] = bn1[t]; sbm2[t] = bm2[t]; }
    for (int t = tid; t < H2*6; t += TPB) sWn2[t] = Wn2[t];
    for (int t = tid; t < 8;   t += TPB) sbn2[t] = (t < 6) ? bn2[t] : 0.0f;
    for (int t = tid; t < 6*MM; t += TPB) sWm1[t] = Wm1[t];
    for (int t = tid; t < MM*H2; t += TPB) sWm2[t] = Wm2[t];
    {
        const float* xb = x + (size_t)b * (NN*3);
        for (int t = tid; t < SLOTS*3; t += TPB) sx[t] = (t < NN*3) ? xb[t] : 0.0f;
    }
    __syncthreads();

    const int node = tid >> 2;          // 0..31 node slot
    const int q    = tid & 3;           // quad lane: output channels [8q, 8q+8)
    const int i    = (node < NN) ? node : (NN-1);  // dummies shadow node 28
    const float xi0 = sx[i*3+0], xi1 = sx[i*3+1], xi2 = sx[i*3+2];

    // ================= KNN (replicated within quad) =================
    {
        float bdist[KK]; int bidx[KK];
#pragma unroll
        for (int s = 0; s < KK; ++s){ bdist[s] = 3.4e38f; bidx[s] = 0; }
        for (int j = 0; j < NN; ++j){
            float dx = xi0 - sx[j*3+0];
            float dy = xi1 - sx[j*3+1];
            float dz = xi2 - sx[j*3+2];
            float dd = dx*dx + dy*dy + dz*dz;
            if (dd < bdist[KK-1]){
                bdist[KK-1] = dd; bidx[KK-1] = j;
#pragma unroll
                for (int s = KK-1; s > 0; --s){
                    if (bdist[s] < bdist[s-1]){
                        float td = bdist[s]; bdist[s] = bdist[s-1]; bdist[s-1] = td;
                        int tj = bidx[s]; bidx[s] = bidx[s-1]; bidx[s-1] = tj;
                    }
                }
            }
        }
        if (q == 0){
#pragma unroll
            for (int s = 0; s < KK; ++s){ snd[node*KK+s] = bdist[s]; snj[node*KK+s] = bidx[s]; }
        }
    }

    // ================= u (regs) / v (smem) tables =================
    float ureg[7], w13r[7];
#pragma unroll
    for (int t = 0; t < 7; ++t){
        int c  = q*7 + t;
        int cc = (c < C1) ? c : 0;
        const float4* ab = (const float4*)(sWab + cc*8);
        float4 a  = ab[0];
        float4 bq = ab[1];
        float u = sbe1[c] + xi0*a.x + xi1*a.y + xi2*a.z;
        float v = xi0*a.w + xi1*bq.x + xi2*bq.y;
        if (c >= C1){ u = 0.0f; v = 0.0f; }
        ureg[t] = u;
        w13r[t] = sw13[c];
        sv[i*C1P + c] = v;
    }
    __syncthreads();   // sv + snd/snj visible block-wide

    // ================= edge loop =================
    ull macc2[4];
#pragma unroll
    for (int p = 0; p < 4; ++p) macc2[p] = splat2(0.0f);

#pragma unroll 1
    for (int k = 0; k < KK; ++k){
        const float d = snd[node*KK + k];
        const int   j = snj[node*KK + k];

        // h phase: each lane computes 7 of the 28 channels
#pragma unroll
        for (int t = 0; t < 7; ++t){
            int c = q*7 + t;
            float hv = ureg[t] + sv[j*C1P + c] + d*w13r[t];
            sh[node*C1P + c] = fsilu(hv);
        }
        __syncwarp();

        // GEMV: m[8q..8q+8) = be2 + h @ We2
        ull m2[4];
        {
            const ulonglong2* bb = (const ulonglong2*)(sbe2 + q*8);
            ulonglong2 b0 = bb[0], b1 = bb[1];
            m2[0] = b0.x; m2[1] = b0.y; m2[2] = b1.x; m2[3] = b1.y;
        }
        const float4* hp = (const float4*)(sh + node*C1P);
#pragma unroll
        for (int p = 0; p < 7; ++p){
            float4 hh = hp[p];
            {
                ull hs = splat2(hh.x);
                const ulonglong2* wp = (const ulonglong2*)(sWe2 + (4*p+0)*MM + q*8);
                ulonglong2 w0 = wp[0], w1 = wp[1];
                ffma2(m2[0], hs, w0.x); ffma2(m2[1], hs, w0.y);
                ffma2(m2[2], hs, w1.x); ffma2(m2[3], hs, w1.y);
            }
            {
                ull hs = splat2(hh.y);
                const ulonglong2* wp = (const ulonglong2*)(sWe2 + (4*p+1)*MM + q*8);
                ulonglong2 w0 = wp[0], w1 = wp[1];
                ffma2(m2[0], hs, w0.x); ffma2(m2[1], hs, w0.y);
                ffma2(m2[2], hs, w1.x); ffma2(m2[3], hs, w1.y);
            }
            {
                ull hs = splat2(hh.z);
                const ulonglong2* wp = (const ulonglong2*)(sWe2 + (4*p+2)*MM + q*8);
                ulonglong2 w0 = wp[0], w1 = wp[1];
                ffma2(m2[0], hs, w0.x); ffma2(m2[1], hs, w0.y);
                ffma2(m2[2], hs, w1.x); ffma2(m2[3], hs, w1.y);
            }
            {
                ull hs = splat2(hh.w);
                const ulonglong2* wp = (const ulonglong2*)(sWe2 + (4*p+3)*MM + q*8);
                ulonglong2 w0 = wp[0], w1 = wp[1];
                ffma2(m2[0], hs, w0.x); ffma2(m2[1], hs, w0.y);
                ffma2(m2[2], hs, w1.x); ffma2(m2[3], hs, w1.y);
            }
        }

        // silu + soft edge gate (quad-reduced) + accumulate
        float2 A = unpack2(m2[0]), Bv = unpack2(m2[1]), Cv = unpack2(m2[2]), Dv = unpack2(m2[3]);
        float mv[8] = {A.x, A.y, Bv.x, Bv.y, Cv.x, Cv.y, Dv.x, Dv.y};
        float g = 0.0f;
#pragma unroll
        for (int r = 0; r < 8; ++r){
            mv[r] = fsilu(mv[r]);
            g += mv[r] * sWg[q*8 + r];
        }
        g += __shfl_xor_sync(0xffffffffu, g, 1);
        g += __shfl_xor_sync(0xffffffffu, g, 2);
        g  = fsigmoid(g + sbg);
        ull gs = splat2(g);
        ffma2(macc2[0], pack2(mv[0], mv[1]), gs);
        ffma2(macc2[1], pack2(mv[2], mv[3]), gs);
        ffma2(macc2[2], pack2(mv[4], mv[5]), gs);
        ffma2(macc2[3], pack2(mv[6], mv[7]), gs);

        __syncwarp();  // quad done reading sh before next k overwrites
    }

    // write m_i to shared (full 32 per node)
    {
        float2 A = unpack2(macc2[0]), Bv = unpack2(macc2[1]),
               Cv = unpack2(macc2[2]), Dv = unpack2(macc2[3]);
        float4* mrow = (float4*)(sm + node*MROW + q*8);
        mrow[0] = make_float4(A.x, A.y, Bv.x, Bv.y);
        mrow[1] = make_float4(Cv.x, Cv.y, Dv.x, Dv.y);
    }
    __syncwarp();

    // ================= node MLP 38->12 (3 outputs per lane) =================
#pragma unroll
    for (int t = 0; t < 3; ++t){
        int c = q*3 + t;
        const float* row = sWn1f + c*NROW;
        float acc = sbn1[c] + xi0*row[0] + xi1*row[1] + xi2*row[2];
        const float4* wp4 = (const float4*)(row + 4);
        const float4* mp4 = (const float4*)(sm + node*MROW);
#pragma unroll
        for (int p = 0; p < 8; ++p){
            float4 wv = wp4[p], mv4 = mp4[p];
            acc += mv4.x*wv.x; acc += mv4.y*wv.y; acc += mv4.z*wv.z; acc += mv4.w*wv.w;
        }
        sh12[node*H2 + c] = fsilu(acc);
    }
    __syncwarp();

    // 12 -> 6 + residual (replicated in quad, q0 stores)
    {
        float fo[6];
#pragma unroll
        for (int o = 0; o < 6; ++o){
            float acc = sbn2[o];
#pragma unroll
            for (int c = 0; c < H2; ++c) acc += sh12[node*H2 + c] * sWn2[c*6 + o];
            float base = (o % 3 == 0) ? xi0 : ((o % 3 == 1) ? xi1 : xi2);
            fo[o] = acc + base;
        }
        if (q == 0){
#pragma unroll
            for (int o = 0; o < 6; ++o) sfo[node*6 + o] = (node < NN) ? fo[o] : 0.0f;
        }
    }
    __syncthreads();

    // ================= pool + head (warp 0) =================
    if (tid < 32){
        const int lane = tid;
        float pool[6];
#pragma unroll
        for (int o = 0; o < 6; ++o) pool[o] = (lane < NN) ? sfo[lane*6 + o] : 0.0f;
#pragma unroll
        for (int o = 0; o < 6; ++o){
#pragma unroll
            for (int off = 16; off > 0; off >>= 1)
                pool[o] += __shfl_xor_sync(0xffffffffu, pool[o], off);
            pool[o] *= (1.0f / 29.0f);
        }
        float hid = sbm1[lane];
#pragma unroll
        for (int c = 0; c < 6; ++c) hid += pool[c] * sWm1[c*MM + lane];
        hid = fmaxf(hid, 0.0f);
        shid[lane] = hid;
        __syncwarp();
        if (lane < H2){
            float acc = sbm2[lane];
#pragma unroll
            for (int h = 0; h < MM; ++h) acc += shid[h] * sWm2[h*H2 + lane];
            out[(size_t)b*(NN*6) + lane] = acc;
        }
    }
    // zero-fill rows 2..28
    for (int t = tid; t < NN*6; t += TPB)
        if (t >= H2) out[(size_t)b*(NN*6) + t] = 0.0f;
}

extern "C" void kernel_launch(void* const* d_in, const int* in_sizes, int n_in,
                              void* d_out, int out_size)
{
    const float* x   = (const float*)d_in[0];
    // d_in[1] = mask (all-true in this problem)
    const float* We1 = (const float*)d_in[2];
    const float* be1 = (const float*)d_in[3];
    const float* We2 = (const float*)d_in[4];
    const float* be2 = (const float*)d_in[5];
    const float* Wg  = (const float*)d_in[6];
    const float* bg  = (const float*)d_in[7];
    const float* Wn1 = (const float*)d_in[8];
    const float* bn1 = (const float*)d_in[9];
    const float* Wn2 = (const float*)d_in[10];
    const float* bn2 = (const float*)d_in[11];
    const float* Wm1 = (const float*)d_in[12];
    const float* bm1 = (const float*)d_in[13];
    const float* Wm2 = (const float*)d_in[14];
    const float* bm2 = (const float*)d_in[15];

    int B = in_sizes[0] / (NN*3);
    arnet_kernel<<<B, TPB>>>(x, We1, be1, We2, be2, Wg, bg,
                             Wn1, bn1, Wn2, bn2, Wm1, bm1, Wm2, bm2,
                             (float*)d_out);
}

// round 3
// speedup vs baseline: 7.4434x; 1.3900x over previous
#include <cuda_runtime.h>

#define TPB 192
#define NN  29
#define KK  6
#define C1  26
#define UST 27
#define MM  32
#define H2  12
#define EROW 36
#define NROW 36

// ---- dynamic smem layout (float offsets) ----
#define W_WE2  0
#define W_WAB  (W_WE2 + C1*MM)        // 832
#define W_W13  (W_WAB + C1*8)         // 1040
#define W_BE2  (W_W13 + 28)           // 1068
#define W_WG   (W_BE2 + MM)           // 1100
#define W_BG   (W_WG + MM)            // 1132
#define W_WN1F (W_BG + 4)             // 1136
#define W_BN1  (W_WN1F + H2*NROW)     // 1568
#define W_WN2  (W_BN1 + H2)           // 1580
#define W_BN2  (W_WN2 + H2*6)         // 1652
#define W_WM1  (W_BN2 + 8)            // 1660
#define W_BM1  (W_WM1 + 6*MM)         // 1852
#define W_WM2  (W_BM1 + MM)           // 1884
#define W_BM2  (W_WM2 + MM*H2)        // 2268
#define PBASE  (W_BM2 + 12)           // 2280 (16B aligned)
#define P_X    0
#define P_SU   96
#define P_SV   (P_SU + 32*UST)        // 960
#define P_SMP  (P_SV + 32*UST)        // 1824
#define P_SH12 (P_SMP + 3*32*EROW)    // 5280
#define P_SFO  (P_SH12 + 32*H2)       // 5664
#define P_SHID (P_SFO + 32*6)         // 5856
#define PBSZ   (P_SHID + 32)          // 5888
#define SMEM_FLOATS (PBASE + 2*PBSZ)  // 14056
#define SMEM_BYTES  (SMEM_FLOATS*4)   // 56224

typedef unsigned long long ull;

__device__ __forceinline__ void ffma2(ull& d, ull a, ull b){
    asm("fma.rn.f32x2 %0, %1, %2, %0;" : "+l"(d) : "l"(a), "l"(b));
}
__device__ __forceinline__ ull splat2(float x){
    ull r; asm("mov.b64 %0, {%1, %1};" : "=l"(r) : "f"(x)); return r;
}
__device__ __forceinline__ float2 unpack2(ull v){
    float2 f; asm("mov.b64 {%0, %1}, %2;" : "=f"(f.x), "=f"(f.y) : "l"(v)); return f;
}
__device__ __forceinline__ float fsigmoid(float v){
    return __fdividef(1.0f, 1.0f + __expf(-v));
}
__device__ __forceinline__ float fsilu(float v){
    return __fdividef(v, 1.0f + __expf(-v));
}

__global__ void __launch_bounds__(TPB, 3)
arnet_kernel(const float* __restrict__ x,
             const float* __restrict__ We1, const float* __restrict__ be1,
             const float* __restrict__ We2, const float* __restrict__ be2,
             const float* __restrict__ Wg,  const float* __restrict__ bgp,
             const float* __restrict__ Wn1, const float* __restrict__ bn1,
             const float* __restrict__ Wn2, const float* __restrict__ bn2,
             const float* __restrict__ Wm1, const float* __restrict__ bm1,
             const float* __restrict__ Wm2, const float* __restrict__ bm2,
             float* __restrict__ out, int Btot)
{
    extern __shared__ float sm[];
    const int tid  = threadIdx.x;
    const int wid  = tid >> 5;
    const int lane = tid & 31;
    const int s    = (wid >= 3) ? 1 : 0;   // batch slot in block
    const int pr   = wid - s*3;            // edge-pair index 0..2
    const int b0   = blockIdx.x * 2;
    const int bS   = min(b0 + s, Btot - 1);

    float* PB = sm + PBASE + s*PBSZ;

    // ================= staging (192 threads) =================
    for (int t = tid; t < C1*MM; t += TPB) sm[W_WE2 + t] = We2[t];
    for (int t = tid; t < C1*8; t += TPB){
        int c = t >> 3, k = t & 7; float v;
        if (k < 3)       v = We1[k*C1 + c]     + We1[(k+3)*C1 + c];
        else if (k < 6)  v = We1[(k+3)*C1 + c] + We1[(k+6)*C1 + c];
        else if (k == 6) v = We1[12*C1 + c];
        else             v = be1[c];
        sm[W_WAB + t] = v;
    }
    for (int t = tid; t < C1; t += TPB) sm[W_W13 + t] = We1[12*C1 + t];
    for (int t = tid; t < MM; t += TPB){
        sm[W_BE2 + t] = be2[t]; sm[W_WG + t] = Wg[t]; sm[W_BM1 + t] = bm1[t];
    }
    if (tid == 0) sm[W_BG] = bgp[0];
    for (int t = tid; t < H2*NROW; t += TPB){
        int c = t / NROW, r = t % NROW; float v = 0.0f;
        if (r < 3)       v = Wn1[r*H2 + c] + Wn1[(r+3)*H2 + c];
        else if (r >= 4) v = Wn1[(6 + (r-4))*H2 + c];
        sm[W_WN1F + t] = v;
    }
    for (int t = tid; t < H2; t += TPB){ sm[W_BN1 + t] = bn1[t]; sm[W_BM2 + t] = bm2[t]; }
    for (int t = tid; t < H2*6; t += TPB) sm[W_WN2 + t] = Wn2[t];
    for (int t = tid; t < 8;    t += TPB) sm[W_BN2 + t] = (t < 6) ? bn2[t] : 0.0f;
    for (int t = tid; t < 6*MM; t += TPB) sm[W_WM1 + t] = Wm1[t];
    for (int t = tid; t < MM*H2; t += TPB) sm[W_WM2 + t] = Wm2[t];
    // x for both batches
    for (int t = tid; t < 192; t += TPB){
        int ss = t / 96, t2 = t % 96;
        int bb = min(b0 + ss, Btot - 1);
        sm[PBASE + ss*PBSZ + P_X + t2] = (t2 < NN*3) ? x[(size_t)bb*(NN*3) + t2] : 0.0f;
    }
    __syncthreads();

    const float* sxB = PB + P_X;
    const int node = lane;
    const int i    = (node < NN) ? node : (NN-1);
    const float xi0 = sxB[i*3+0], xi1 = sxB[i*3+1], xi2 = sxB[i*3+2];

    // ================= KNN (per thread; 3x replicated per batch) =================
    float dA, dB; int jA, jB;
    {
        float bd[KK]; int bi[KK];
#pragma unroll
        for (int t = 0; t < KK; ++t){ bd[t] = 3.4e38f; bi[t] = 0; }
        for (int j = 0; j < NN; ++j){
            float dx = xi0 - sxB[j*3+0];
            float dy = xi1 - sxB[j*3+1];
            float dz = xi2 - sxB[j*3+2];
            float dd = dx*dx + dy*dy + dz*dz;
            if (dd < bd[KK-1]){
                bd[KK-1] = dd; bi[KK-1] = j;
#pragma unroll
                for (int t = KK-1; t > 0; --t){
                    if (bd[t] < bd[t-1]){
                        float td = bd[t]; bd[t] = bd[t-1]; bd[t-1] = td;
                        int tj = bi[t]; bi[t] = bi[t-1]; bi[t-1] = tj;
                    }
                }
            }
        }
        if (pr == 0){ dA = bd[0]; jA = bi[0]; dB = bd[1]; jB = bi[1]; }
        else if (pr == 1){ dA = bd[2]; jA = bi[2]; dB = bd[3]; jB = bi[3]; }
        else { dA = bd[4]; jA = bi[4]; dB = bd[5]; jB = bi[5]; }
    }

    // ================= u/v tables: warp pr covers its c-range =================
    {
        const float x0 = sxB[lane*3+0], x1 = sxB[lane*3+1], x2 = sxB[lane*3+2];
        int c0 = pr*9, c1e = (pr == 2) ? C1 : (pr*9 + 9);
        for (int c = c0; c < c1e; ++c){
            const float4* ab = (const float4*)(sm + W_WAB + c*8);
            float4 a = ab[0], bb = ab[1];
            PB[P_SU + lane*UST + c] = bb.w + x0*a.x + x1*a.y + x2*a.z;
            PB[P_SV + lane*UST + c] = x0*a.w + x1*bb.x + x2*bb.y;
        }
    }
    __syncthreads();

    // ================= edge-pair loop =================
    ull mA[16], mB[16];
    {
        const ulonglong2* bp = (const ulonglong2*)(sm + W_BE2);
#pragma unroll
        for (int t = 0; t < 8; ++t){
            ulonglong2 v = bp[t];
            mA[2*t] = v.x; mA[2*t+1] = v.y;
            mB[2*t] = v.x; mB[2*t+1] = v.y;
        }
    }
    {
        const float* ub = PB + P_SU + i*UST;
        const float* va = PB + P_SV + jA*UST;
        const float* vb = PB + P_SV + jB*UST;
        const float* w13 = sm + W_W13;
#pragma unroll
        for (int c = 0; c < C1; ++c){
            float uu = ub[c];
            float wc = w13[c];
            float hA = fsilu(uu + va[c] + dA*wc);
            float hB = fsilu(uu + vb[c] + dB*wc);
            ull h2A = splat2(hA);
            ull h2B = splat2(hB);
            const ulonglong2* wr = (const ulonglong2*)(sm + W_WE2 + c*MM);
#pragma unroll
            for (int t = 0; t < 8; ++t){
                ulonglong2 ww = wr[t];
                ffma2(mA[2*t],   h2A, ww.x);
                ffma2(mA[2*t+1], h2A, ww.y);
                ffma2(mB[2*t],   h2B, ww.x);
                ffma2(mB[2*t+1], h2B, ww.y);
            }
        }
    }

    // ---- epilogue: silu + gate per edge, pair-sum in regs ----
    {
        float mvA[MM], mvB[MM];
        float gA = sm[W_BG], gB = sm[W_BG];
#pragma unroll
        for (int t = 0; t < 16; ++t){
            float2 fa = unpack2(mA[t]);
            float2 fb = unpack2(mB[t]);
            float a0 = fsilu(fa.x), a1 = fsilu(fa.y);
            float b0v = fsilu(fb.x), b1v = fsilu(fb.y);
            float wg0 = sm[W_WG + 2*t], wg1 = sm[W_WG + 2*t + 1];
            gA += a0*wg0 + a1*wg1;
            gB += b0v*wg0 + b1v*wg1;
            mvA[2*t] = a0; mvA[2*t+1] = a1;
            mvB[2*t] = b0v; mvB[2*t+1] = b1v;
        }
        gA = fsigmoid(gA);
        gB = fsigmoid(gB);
        float4* orow = (float4*)(PB + P_SMP + (pr*32 + node)*EROW);
#pragma unroll
        for (int t = 0; t < 8; ++t){
            float4 o;
            o.x = mvA[4*t+0]*gA + mvB[4*t+0]*gB;
            o.y = mvA[4*t+1]*gA + mvB[4*t+1]*gB;
            o.z = mvA[4*t+2]*gA + mvB[4*t+2]*gB;
            o.w = mvA[4*t+3]*gA + mvB[4*t+3]*gB;
            orow[t] = o;
        }
    }
    __syncthreads();

    // ================= node MLP: (node2, t3) trio, 4 Wn1 outputs each =================
    {
        const int t96  = (tid < 96) ? tid : tid - 96;
        const int node2 = t96 / 3;
        const int t3    = t96 % 3;
        float msum[MM];
        float4* ms4 = (float4*)msum;
#pragma unroll
        for (int t = 0; t < 8; ++t) ms4[t] = make_float4(0.f, 0.f, 0.f, 0.f);
#pragma unroll
        for (int e = 0; e < 3; ++e){
            const float4* rr = (const float4*)(PB + P_SMP + (e*32 + node2)*EROW);
#pragma unroll
            for (int t = 0; t < 8; ++t){
                float4 v = rr[t];
                ms4[t].x += v.x; ms4[t].y += v.y; ms4[t].z += v.z; ms4[t].w += v.w;
            }
        }
        const float y0 = sxB[node2*3+0], y1 = sxB[node2*3+1], y2 = sxB[node2*3+2];
#pragma unroll
        for (int k = 0; k < 4; ++k){
            int c = t3*4 + k;
            const float* row = sm + W_WN1F + c*NROW;
            float acc = sm[W_BN1 + c] + y0*row[0] + y1*row[1] + y2*row[2];
            const float4* rw = (const float4*)(row + 4);
#pragma unroll
            for (int t = 0; t < 8; ++t){
                float4 wv = rw[t];
                acc += msum[4*t+0]*wv.x; acc += msum[4*t+1]*wv.y;
                acc += msum[4*t+2]*wv.z; acc += msum[4*t+3]*wv.w;
            }
            PB[P_SH12 + node2*H2 + c] = fsilu(acc);
        }
        __syncthreads();

        // 12 -> 6 + residual: 2 outputs per trio-thread
        if (node2 < NN){
#pragma unroll
            for (int oo = 0; oo < 2; ++oo){
                int o = t3*2 + oo;
                float acc = sm[W_BN2 + o];
#pragma unroll
                for (int c = 0; c < H2; ++c)
                    acc += PB[P_SH12 + node2*H2 + c] * sm[W_WN2 + c*6 + o];
                float base = (o % 3 == 0) ? y0 : ((o % 3 == 1) ? y1 : y2);
                PB[P_SFO + node2*6 + o] = acc + base;
            }
        }
    }
    __syncthreads();

    // ================= pool + head (warp 0 -> batch 0, warp 3 -> batch 1) =================
    {
        int pl = -1, pb = 0;
        if (tid < 32){ pl = tid; pb = 0; }
        else if (tid >= 96 && tid < 128){ pl = tid - 96; pb = 1; }
        if (pl >= 0){
            float* PBp = sm + PBASE + pb*PBSZ;
            int bb = min(b0 + pb, Btot - 1);
            float pool[6];
#pragma unroll
            for (int o = 0; o < 6; ++o) pool[o] = (pl < NN) ? PBp[P_SFO + pl*6 + o] : 0.0f;
#pragma unroll
            for (int o = 0; o < 6; ++o){
#pragma unroll
                for (int off = 16; off > 0; off >>= 1)
                    pool[o] += __shfl_xor_sync(0xffffffffu, pool[o], off);
                pool[o] *= (1.0f / 29.0f);
            }
            float hid = sm[W_BM1 + pl];
#pragma unroll
            for (int c = 0; c < 6; ++c) hid += pool[c] * sm[W_WM1 + c*MM + pl];
            hid = fmaxf(hid, 0.0f);
            PBp[P_SHID + pl] = hid;
            __syncwarp();
            if (pl < H2){
                float acc = sm[W_BM2 + pl];
#pragma unroll
                for (int h = 0; h < MM; ++h) acc += PBp[P_SHID + h] * sm[W_WM2 + h*H2 + pl];
                out[(size_t)bb*(NN*6) + pl] = acc;
            }
        }
    }
    // zero-fill rows 2..28 for both batches
    for (int t = tid; t < 2*NN*6; t += TPB){
        int ss = t / (NN*6), r = t % (NN*6);
        if (r >= H2){
            int bb = min(b0 + ss, Btot - 1);
            out[(size_t)bb*(NN*6) + r] = 0.0f;
        }
    }
}

extern "C" void kernel_launch(void* const* d_in, const int* in_sizes, int n_in,
                              void* d_out, int out_size)
{
    const float* x   = (const float*)d_in[0];
    // d_in[1] = mask (all-true in this problem)
    const float* We1 = (const float*)d_in[2];
    const float* be1 = (const float*)d_in[3];
    const float* We2 = (const float*)d_in[4];
    const float* be2 = (const float*)d_in[5];
    const float* Wg  = (const float*)d_in[6];
    const float* bg  = (const float*)d_in[7];
    const float* Wn1 = (const float*)d_in[8];
    const float* bn1 = (const float*)d_in[9];
    const float* Wn2 = (const float*)d_in[10];
    const float* bn2 = (const float*)d_in[11];
    const float* Wm1 = (const float*)d_in[12];
    const float* bm1 = (const float*)d_in[13];
    const float* Wm2 = (const float*)d_in[14];
    const float* bm2 = (const float*)d_in[15];

    int B = in_sizes[0] / (NN*3);
    static int attr_done = 0;
    cudaFuncSetAttribute(arnet_kernel, cudaFuncAttributeMaxDynamicSharedMemorySize, SMEM_BYTES);
    (void)attr_done;
    int grid = (B + 1) / 2;
    arnet_kernel<<<grid, TPB, SMEM_BYTES>>>(x, We1, be1, We2, be2, Wg, bg,
                                            Wn1, bn1, Wn2, bn2, Wm1, bm1, Wm2, bm2,
                                            (float*)d_out, B);
}

// round 4
// speedup vs baseline: 7.7562x; 1.0420x over previous
#include <cuda_runtime.h>

#define TPB 192
#define NN  29
#define KK  6
#define C1  26
#define UST 27
#define MM  32
#define H2  12
#define EROW 36
#define NROW 36

// ---- dynamic smem layout (float offsets) ----
#define W_WE2  0
#define W_WAB  (W_WE2 + C1*MM)        // 832
#define W_W13  (W_WAB + C1*8)         // 1040
#define W_BE2  (W_W13 + 28)           // 1068
#define W_WG   (W_BE2 + MM)           // 1100
#define W_BG   (W_WG + MM)            // 1132
#define W_WN1F (W_BG + 4)             // 1136
#define W_BN1  (W_WN1F + H2*NROW)     // 1568
#define W_WN2  (W_BN1 + H2)           // 1580
#define W_BN2  (W_WN2 + H2*6)         // 1652
#define W_WM1  (W_BN2 + 8)            // 1660
#define W_BM1  (W_WM1 + 6*MM)         // 1852
#define W_WM2  (W_BM1 + MM)           // 1884
#define W_BM2  (W_WM2 + MM*H2)        // 2268
#define PBASE  (W_BM2 + 12)           // 2280
// per-batch scratch
#define P_X    0
#define P_SU   96
#define P_SV   (P_SU + 32*UST)        // 960
#define P_SMP  (P_SV + 32*UST)        // 1824
#define P_SND  (P_SMP + 3*32*EROW)    // 5280
#define P_SNJ  (P_SND + 32*KK)        // 5472
#define PBSZ   (P_SNJ + 32*KK)        // 5664
// aliases (valid after edge loop; su region is dead by then)
#define P_SH12 P_SU                   // 384 floats
#define P_SFO  (P_SU + 384)           // 192 floats
#define P_SHID (P_SU + 576)           // 32 floats
#define SMEM_FLOATS (PBASE + 2*PBSZ)  // 13608
#define SMEM_BYTES  (SMEM_FLOATS*4)   // 54432

typedef unsigned long long ull;

__device__ __forceinline__ void ffma2(ull& d, ull a, ull b){
    asm("fma.rn.f32x2 %0, %1, %2, %0;" : "+l"(d) : "l"(a), "l"(b));
}
__device__ __forceinline__ ull fmul2(ull a, ull b){
    ull r; asm("mul.rn.f32x2 %0, %1, %2;" : "=l"(r) : "l"(a), "l"(b)); return r;
}
__device__ __forceinline__ ull splat2(float x){
    ull r; asm("mov.b64 %0, {%1, %1};" : "=l"(r) : "f"(x)); return r;
}
__device__ __forceinline__ ull pack2(float x, float y){
    ull r; asm("mov.b64 %0, {%1, %2};" : "=l"(r) : "f"(x), "f"(y)); return r;
}
__device__ __forceinline__ float2 unpack2(ull v){
    float2 f; asm("mov.b64 {%0, %1}, %2;" : "=f"(f.x), "=f"(f.y) : "l"(v)); return f;
}
__device__ __forceinline__ float ftanh(float v){
    float r; asm("tanh.approx.f32 %0, %1;" : "=f"(r) : "f"(v)); return r;
}
__device__ __forceinline__ float fsigmoid(float v){
    return fmaf(0.5f, ftanh(0.5f*v), 0.5f);
}
__device__ __forceinline__ float fsilu(float v){
    return v * fsigmoid(v);
}

__global__ void __launch_bounds__(TPB, 4)
arnet_kernel(const float* __restrict__ x,
             const float* __restrict__ We1, const float* __restrict__ be1,
             const float* __restrict__ We2, const float* __restrict__ be2,
             const float* __restrict__ Wg,  const float* __restrict__ bgp,
             const float* __restrict__ Wn1, const float* __restrict__ bn1,
             const float* __restrict__ Wn2, const float* __restrict__ bn2,
             const float* __restrict__ Wm1, const float* __restrict__ bm1,
             const float* __restrict__ Wm2, const float* __restrict__ bm2,
             float* __restrict__ out, int Btot)
{
    extern __shared__ float sm[];
    const int tid  = threadIdx.x;
    const int wid  = tid >> 5;
    const int lane = tid & 31;
    const int s    = (wid >= 3) ? 1 : 0;   // batch slot in block
    const int pr   = wid - s*3;            // edge-pair index 0..2
    const int b0   = blockIdx.x * 2;

    float* PB = sm + PBASE + s*PBSZ;

    // ================= staging (192 threads) =================
    for (int t = tid; t < C1*MM; t += TPB) sm[W_WE2 + t] = We2[t];
    for (int t = tid; t < C1*8; t += TPB){
        int c = t >> 3, k = t & 7; float v;
        if (k < 3)       v = We1[k*C1 + c]     + We1[(k+3)*C1 + c];
        else if (k < 6)  v = We1[(k+3)*C1 + c] + We1[(k+6)*C1 + c];
        else if (k == 6) v = We1[12*C1 + c];
        else             v = be1[c];
        sm[W_WAB + t] = v;
    }
    for (int t = tid; t < C1; t += TPB) sm[W_W13 + t] = We1[12*C1 + t];
    for (int t = tid; t < MM; t += TPB){
        sm[W_BE2 + t] = be2[t]; sm[W_WG + t] = Wg[t]; sm[W_BM1 + t] = bm1[t];
    }
    if (tid == 0) sm[W_BG] = bgp[0];
    for (int t = tid; t < H2*NROW; t += TPB){
        int c = t / NROW, r = t % NROW; float v = 0.0f;
        if (r < 3)       v = Wn1[r*H2 + c] + Wn1[(r+3)*H2 + c];
        else if (r >= 4) v = Wn1[(6 + (r-4))*H2 + c];
        sm[W_WN1F + t] = v;
    }
    for (int t = tid; t < H2; t += TPB){ sm[W_BN1 + t] = bn1[t]; sm[W_BM2 + t] = bm2[t]; }
    for (int t = tid; t < H2*6; t += TPB) sm[W_WN2 + t] = Wn2[t];
    for (int t = tid; t < 8;    t += TPB) sm[W_BN2 + t] = (t < 6) ? bn2[t] : 0.0f;
    for (int t = tid; t < 6*MM; t += TPB) sm[W_WM1 + t] = Wm1[t];
    for (int t = tid; t < MM*H2; t += TPB) sm[W_WM2 + t] = Wm2[t];
    // x for both batches (pad with zeros)
    for (int t = tid; t < 192; t += TPB){
        int ss = t / 96, t2 = t % 96;
        int bb = min(b0 + ss, Btot - 1);
        sm[PBASE + ss*PBSZ + P_X + t2] = (t2 < NN*3) ? x[(size_t)bb*(NN*3) + t2] : 0.0f;
    }
    __syncthreads();

    const float* sxB = PB + P_X;
    const int node = lane;
    const int i    = (node < NN) ? node : (NN-1);

    // ================= phase 1 (specialized): KNN | u/v tables =================
    if (pr == 0){
        // KNN for this batch, once (warp 0 / warp 3)
        const float xi0 = sxB[i*3+0], xi1 = sxB[i*3+1], xi2 = sxB[i*3+2];
        float bd[KK]; int bi[KK];
#pragma unroll
        for (int t = 0; t < KK; ++t){ bd[t] = 3.4e38f; bi[t] = 0; }
        for (int j = 0; j < NN; ++j){
            float dx = xi0 - sxB[j*3+0];
            float dy = xi1 - sxB[j*3+1];
            float dz = xi2 - sxB[j*3+2];
            float dd = dx*dx + dy*dy + dz*dz;
            if (dd < bd[KK-1]){
                bd[KK-1] = dd; bi[KK-1] = j;
#pragma unroll
                for (int t = KK-1; t > 0; --t){
                    if (bd[t] < bd[t-1]){
                        float td = bd[t]; bd[t] = bd[t-1]; bd[t-1] = td;
                        int tj = bi[t]; bi[t] = bi[t-1]; bi[t-1] = tj;
                    }
                }
            }
        }
#pragma unroll
        for (int t = 0; t < KK; ++t){
            PB[P_SND + lane*KK + t] = bd[t];
            ((int*)(PB + P_SNJ))[lane*KK + t] = bi[t];
        }
    } else {
        // u/v tables: warp pr covers its channel range (13 each)
        const float x0 = sxB[lane*3+0], x1 = sxB[lane*3+1], x2 = sxB[lane*3+2];
        const int c0 = (pr == 1) ? 0 : 13;
        const int cE = (pr == 1) ? 13 : C1;
        for (int c = c0; c < cE; ++c){
            const float4* ab = (const float4*)(sm + W_WAB + c*8);
            float4 a = ab[0], bb = ab[1];
            PB[P_SU + lane*UST + c] = bb.w + x0*a.x + x1*a.y + x2*a.z;
            PB[P_SV + lane*UST + c] = x0*a.w + x1*bb.x + x2*bb.y;
        }
    }
    __syncthreads();

    const float dA = PB[P_SND + node*KK + pr*2 + 0];
    const float dB = PB[P_SND + node*KK + pr*2 + 1];
    const int   jA = ((const int*)(PB + P_SNJ))[node*KK + pr*2 + 0];
    const int   jB = ((const int*)(PB + P_SNJ))[node*KK + pr*2 + 1];

    // ================= edge-pair GEMV =================
    ull mA[16], mB[16];
    {
        const ulonglong2* bp = (const ulonglong2*)(sm + W_BE2);
#pragma unroll
        for (int t = 0; t < 8; ++t){
            ulonglong2 v = bp[t];
            mA[2*t] = v.x; mA[2*t+1] = v.y;
            mB[2*t] = v.x; mB[2*t+1] = v.y;
        }
    }
    {
        const float* ub  = PB + P_SU + i*UST;
        const float* va  = PB + P_SV + jA*UST;
        const float* vb  = PB + P_SV + jB*UST;
        const float* w13 = sm + W_W13;
#pragma unroll
        for (int c = 0; c < C1; ++c){
            float uu = ub[c];
            float wc = w13[c];
            float hA = fsilu(uu + va[c] + dA*wc);
            float hB = fsilu(uu + vb[c] + dB*wc);
            ull h2A = splat2(hA);
            ull h2B = splat2(hB);
            const ulonglong2* wr = (const ulonglong2*)(sm + W_WE2 + c*MM);
#pragma unroll
            for (int t = 0; t < 8; ++t){
                ulonglong2 ww = wr[t];
                ffma2(mA[2*t],   h2A, ww.x);
                ffma2(mA[2*t+1], h2A, ww.y);
                ffma2(mB[2*t],   h2B, ww.x);
                ffma2(mB[2*t+1], h2B, ww.y);
            }
        }
    }

    // ---- epilogue: silu (in place) + gate, pair-sum, store ----
    {
        float gA = sm[W_BG], gB = gA;
#pragma unroll
        for (int t = 0; t < 16; ++t){
            float2 fa = unpack2(mA[t]);
            float2 fb = unpack2(mB[t]);
            fa.x = fsilu(fa.x); fa.y = fsilu(fa.y);
            fb.x = fsilu(fb.x); fb.y = fsilu(fb.y);
            float wg0 = sm[W_WG + 2*t], wg1 = sm[W_WG + 2*t + 1];
            gA += fa.x*wg0 + fa.y*wg1;
            gB += fb.x*wg0 + fb.y*wg1;
            mA[t] = pack2(fa.x, fa.y);
            mB[t] = pack2(fb.x, fb.y);
        }
        gA = fsigmoid(gA);
        gB = fsigmoid(gB);
        ull gsA = splat2(gA), gsB = splat2(gB);
        float4* orow = (float4*)(PB + P_SMP + (pr*32 + node)*EROW);
#pragma unroll
        for (int t = 0; t < 8; ++t){
            ull o0 = fmul2(mA[2*t],   gsA); ffma2(o0, mB[2*t],   gsB);
            ull o1 = fmul2(mA[2*t+1], gsA); ffma2(o1, mB[2*t+1], gsB);
            float2 a = unpack2(o0), b2 = unpack2(o1);
            orow[t] = make_float4(a.x, a.y, b2.x, b2.y);
        }
    }
    __syncthreads();   // P_SMP complete; su region now reusable

    // ================= node MLP: (node2, t3) trio, 4 Wn1 outputs each =================
    {
        const int t96   = (tid < 96) ? tid : tid - 96;
        const int node2 = t96 / 3;
        const int t3    = t96 % 3;
        float msum[MM];
        float4* ms4 = (float4*)msum;
#pragma unroll
        for (int t = 0; t < 8; ++t) ms4[t] = make_float4(0.f, 0.f, 0.f, 0.f);
#pragma unroll
        for (int e = 0; e < 3; ++e){
            const float4* rr = (const float4*)(PB + P_SMP + (e*32 + node2)*EROW);
#pragma unroll
            for (int t = 0; t < 8; ++t){
                float4 v = rr[t];
                ms4[t].x += v.x; ms4[t].y += v.y; ms4[t].z += v.z; ms4[t].w += v.w;
            }
        }
        const float y0 = sxB[node2*3+0], y1 = sxB[node2*3+1], y2 = sxB[node2*3+2];
        float h4[4];
#pragma unroll
        for (int k = 0; k < 4; ++k){
            int c = t3*4 + k;
            const float* row = sm + W_WN1F + c*NROW;
            float acc = sm[W_BN1 + c] + y0*row[0] + y1*row[1] + y2*row[2];
            const float4* rw = (const float4*)(row + 4);
#pragma unroll
            for (int t = 0; t < 8; ++t){
                float4 wv = rw[t];
                acc += msum[4*t+0]*wv.x; acc += msum[4*t+1]*wv.y;
                acc += msum[4*t+2]*wv.z; acc += msum[4*t+3]*wv.w;
            }
            h4[k] = fsilu(acc);
        }
        __syncthreads();   // everyone done with su-region reads (none) — safe to write sh12
#pragma unroll
        for (int k = 0; k < 4; ++k)
            PB[P_SH12 + node2*H2 + t3*4 + k] = h4[k];
        __syncthreads();

        // 12 -> 6 + residual: 2 outputs per trio-thread
        if (node2 < NN){
#pragma unroll
            for (int oo = 0; oo < 2; ++oo){
                int o = t3*2 + oo;
                float acc = sm[W_BN2 + o];
#pragma unroll
                for (int c = 0; c < H2; ++c)
                    acc += PB[P_SH12 + node2*H2 + c] * sm[W_WN2 + c*6 + o];
                float base = (o % 3 == 0) ? y0 : ((o % 3 == 1) ? y1 : y2);
                PB[P_SFO + node2*6 + o] = acc + base;
            }
        }
    }
    __syncthreads();

    // ================= pool + head (warp 0 -> batch 0, warp 3 -> batch 1) =================
    {
        int pl = -1, pb = 0;
        if (tid < 32){ pl = tid; pb = 0; }
        else if (tid >= 96 && tid < 128){ pl = tid - 96; pb = 1; }
        if (pl >= 0){
            float* PBp = sm + PBASE + pb*PBSZ;
            int bb = min(b0 + pb, Btot - 1);
            float pool[6];
#pragma unroll
            for (int o = 0; o < 6; ++o) pool[o] = (pl < NN) ? PBp[P_SFO + pl*6 + o] : 0.0f;
#pragma unroll
            for (int o = 0; o < 6; ++o){
#pragma unroll
                for (int off = 16; off > 0; off >>= 1)
                    pool[o] += __shfl_xor_sync(0xffffffffu, pool[o], off);
                pool[o] *= (1.0f / 29.0f);
            }
            float hid = sm[W_BM1 + pl];
#pragma unroll
            for (int c = 0; c < 6; ++c) hid += pool[c] * sm[W_WM1 + c*MM + pl];
            hid = fmaxf(hid, 0.0f);
            PBp[P_SHID + pl] = hid;
            __syncwarp();
            if (pl < H2){
                float acc = sm[W_BM2 + pl];
#pragma unroll
                for (int h = 0; h < MM; ++h) acc += PBp[P_SHID + h] * sm[W_WM2 + h*H2 + pl];
                out[(size_t)bb*(NN*6) + pl] = acc;
            }
        }
    }
    // zero-fill rows 2..28 for both batches
    for (int t = tid; t < 2*NN*6; t += TPB){
        int ss = t / (NN*6), r = t % (NN*6);
        if (r >= H2){
            int bb = min(b0 + ss, Btot - 1);
            out[(size_t)bb*(NN*6) + r] = 0.0f;
        }
    }
}

extern "C" void kernel_launch(void* const* d_in, const int* in_sizes, int n_in,
                              void* d_out, int out_size)
{
    const float* x   = (const float*)d_in[0];
    // d_in[1] = mask (all-true in this problem)
    const float* We1 = (const float*)d_in[2];
    const float* be1 = (const float*)d_in[3];
    const float* We2 = (const float*)d_in[4];
    const float* be2 = (const float*)d_in[5];
    const float* Wg  = (const float*)d_in[6];
    const float* bg  = (const float*)d_in[7];
    const float* Wn1 = (const float*)d_in[8];
    const float* bn1 = (const float*)d_in[9];
    const float* Wn2 = (const float*)d_in[10];
    const float* bn2 = (const float*)d_in[11];
    const float* Wm1 = (const float*)d_in[12];
    const float* bm1 = (const float*)d_in[13];
    const float* Wm2 = (const float*)d_in[14];
    const float* bm2 = (const float*)d_in[15];

    int B = in_sizes[0] / (NN*3);
    cudaFuncSetAttribute(arnet_kernel, cudaFuncAttributeMaxDynamicSharedMemorySize, SMEM_BYTES);
    int grid = (B + 1) / 2;
    arnet_kernel<<<grid, TPB, SMEM_BYTES>>>(x, We1, be1, We2, be2, Wg, bg,
                                            Wn1, bn1, Wn2, bn2, Wm1, bm1, Wm2, bm2,
                                            (float*)d_out, B);
}